// round 8
// baseline (speedup 1.0000x reference)
#include <cuda_runtime.h>

// y[b,c] = b_fc[c] + dot(h[b,0,:], V[c,:]),  V = W_fc @ W_emb  ([2,768])
// (TreeLSTM scan in the reference is dead code; adj and recurrent weights unused.)
// B=32, N=128, FI=768, FO=128.
//
// SINGLE block, single graph node, no cross-block communication:
//   warps 0-23 : V partials (each thread: one f-quad x 32 o's, coalesced LDG.128)
//   warps 24-31: stage all h[b,0,:] rows into shared (overlaps phase 1)
//   barrier -> fold partials -> barrier -> warp b computes y[b,:].

#define B_   32
#define N_   128
#define FI_  768
#define FO_  128
#define NQ   (FI_ / 4)          // 192 f-quads

// dynamic smem layout (float4 units):
//   s_part[4][2][NQ]  : 1536   (V partials per o-group)
//   s_V   [2][NQ]     : 384
//   s_h   [B_*NQ]     : 6144   (all 32 h rows)
#define OFF_PART 0
#define OFF_V    1536
#define OFF_H    1920
#define SMEM_F4  8064
#define SMEM_BYTES (SMEM_F4 * 16)

__global__ __launch_bounds__(1024, 1)
void rvnn_single(const float* __restrict__ h,      // [B,N,FI]
                 const float* __restrict__ W_emb,  // [FO,FI]
                 const float* __restrict__ W_fc,   // [2,FO]
                 const float* __restrict__ b_fc,   // [2]
                 float* __restrict__ y)            // [B,2]
{
    extern __shared__ float4 smem[];
    float4* s_part = smem + OFF_PART;   // [og][c][q] = og*384 + c*192 + q
    float4* s_V    = smem + OFF_V;      // [c][q]
    float4* s_h    = smem + OFF_H;      // [b*192 + q]

    const int t = threadIdx.x;

    if (t < 768) {
        // ---- Phase 1: V partials. og = o-group (32 o's), q = f-quad. ----
        const int og = t / NQ;          // 0..3
        const int q  = t % NQ;          // 0..191 (warp-consecutive)

        const float4* wemb4 = reinterpret_cast<const float4*>(W_emb);
        const float4* wfc4  = reinterpret_cast<const float4*>(W_fc);

        float4 a0 = make_float4(0.f, 0.f, 0.f, 0.f);
        float4 a1 = make_float4(0.f, 0.f, 0.f, 0.f);

        #pragma unroll
        for (int j = 0; j < 8; ++j) {            // 8 o-quads of 4
            const int o4 = og * 8 + j;           // o-quad index within 0..31
            float4 f0 = __ldg(&wfc4[o4]);        // W_fc[0][o4*4..+3] (broadcast)
            float4 f1 = __ldg(&wfc4[FO_ / 4 + o4]);

            // 4 W_emb rows, each: one float4 at f-quad q (coalesced across lanes)
            float4 w0 = __ldg(&wemb4[(size_t)(o4 * 4 + 0) * NQ + q]);
            float4 w1 = __ldg(&wemb4[(size_t)(o4 * 4 + 1) * NQ + q]);
            float4 w2 = __ldg(&wemb4[(size_t)(o4 * 4 + 2) * NQ + q]);
            float4 w3 = __ldg(&wemb4[(size_t)(o4 * 4 + 3) * NQ + q]);

            a0.x = fmaf(f0.x, w0.x, a0.x); a0.y = fmaf(f0.x, w0.y, a0.y);
            a0.z = fmaf(f0.x, w0.z, a0.z); a0.w = fmaf(f0.x, w0.w, a0.w);
            a1.x = fmaf(f1.x, w0.x, a1.x); a1.y = fmaf(f1.x, w0.y, a1.y);
            a1.z = fmaf(f1.x, w0.z, a1.z); a1.w = fmaf(f1.x, w0.w, a1.w);

            a0.x = fmaf(f0.y, w1.x, a0.x); a0.y = fmaf(f0.y, w1.y, a0.y);
            a0.z = fmaf(f0.y, w1.z, a0.z); a0.w = fmaf(f0.y, w1.w, a0.w);
            a1.x = fmaf(f1.y, w1.x, a1.x); a1.y = fmaf(f1.y, w1.y, a1.y);
            a1.z = fmaf(f1.y, w1.z, a1.z); a1.w = fmaf(f1.y, w1.w, a1.w);

            a0.x = fmaf(f0.z, w2.x, a0.x); a0.y = fmaf(f0.z, w2.y, a0.y);
            a0.z = fmaf(f0.z, w2.z, a0.z); a0.w = fmaf(f0.z, w2.w, a0.w);
            a1.x = fmaf(f1.z, w2.x, a1.x); a1.y = fmaf(f1.z, w2.y, a1.y);
            a1.z = fmaf(f1.z, w2.z, a1.z); a1.w = fmaf(f1.z, w2.w, a1.w);

            a0.x = fmaf(f0.w, w3.x, a0.x); a0.y = fmaf(f0.w, w3.y, a0.y);
            a0.z = fmaf(f0.w, w3.z, a0.z); a0.w = fmaf(f0.w, w3.w, a0.w);
            a1.x = fmaf(f1.w, w3.x, a1.x); a1.y = fmaf(f1.w, w3.y, a1.y);
            a1.z = fmaf(f1.w, w3.z, a1.z); a1.w = fmaf(f1.w, w3.w, a1.w);
        }

        s_part[og * 384 + 0 * NQ + q] = a0;
        s_part[og * 384 + 1 * NQ + q] = a1;
    } else {
        // ---- Warps 24-31: stage h[0..31][0][:] into shared. ----
        const int tt = t - 768;                   // 0..255
        #pragma unroll
        for (int r = 0; r < 24; ++r) {
            const int idx = r * 256 + tt;         // 0..6143 = b*192 + q
            const int b = idx / NQ, q = idx % NQ;
            s_h[idx] = __ldg(reinterpret_cast<const float4*>(
                           h + (size_t)b * N_ * FI_) + q);
        }
    }
    __syncthreads();

    // ---- Fold og-partials into V. ----
    if (t < 2 * NQ) {
        const int c = t / NQ, q = t % NQ;
        float4 p0 = s_part[0 * 384 + c * NQ + q];
        float4 p1 = s_part[1 * 384 + c * NQ + q];
        float4 p2 = s_part[2 * 384 + c * NQ + q];
        float4 p3 = s_part[3 * 384 + c * NQ + q];
        s_V[c * NQ + q] = make_float4(p0.x + p1.x + p2.x + p3.x,
                                      p0.y + p1.y + p2.y + p3.y,
                                      p0.z + p1.z + p2.z + p3.z,
                                      p0.w + p1.w + p2.w + p3.w);
    }
    __syncthreads();

    // ---- Phase 2: warp w = batch b; 6 quads per lane; shfl reduce. ----
    {
        const int b    = t >> 5;
        const int lane = t & 31;

        float a0 = 0.f, a1 = 0.f;
        #pragma unroll
        for (int k = 0; k < 6; ++k) {
            const int q = k * 32 + lane;
            float4 hv = s_h[b * NQ + q];
            float4 v0 = s_V[0 * NQ + q];
            float4 v1 = s_V[1 * NQ + q];
            a0 = fmaf(hv.x, v0.x, fmaf(hv.y, v0.y, fmaf(hv.z, v0.z, fmaf(hv.w, v0.w, a0))));
            a1 = fmaf(hv.x, v1.x, fmaf(hv.y, v1.y, fmaf(hv.z, v1.z, fmaf(hv.w, v1.w, a1))));
        }

        #pragma unroll
        for (int off = 16; off > 0; off >>= 1) {
            a0 += __shfl_down_sync(0xffffffffu, a0, off);
            a1 += __shfl_down_sync(0xffffffffu, a1, off);
        }

        if (lane == 0) {
            y[b * 2 + 0] = a0 + __ldg(&b_fc[0]);
            y[b * 2 + 1] = a1 + __ldg(&b_fc[1]);
        }
    }
}

extern "C" void kernel_launch(void* const* d_in, const int* in_sizes, int n_in,
                              void* d_out, int out_size)
{
    // metadata order: h, adj, W_emb, W_ioux, b_ioux, W_iouh, b_iouh,
    //                 W_coux, b_coux, W_couh, b_couh, W_fc, b_fc
    const float* h     = (const float*)d_in[0];
    const float* W_emb = (const float*)d_in[2];
    const float* W_fc  = (const float*)d_in[11];
    const float* b_fc  = (const float*)d_in[12];
    float* y = (float*)d_out;

    static bool attr_set = false;   // idempotent host-side attribute, not device state
    if (!attr_set) {
        cudaFuncSetAttribute(rvnn_single,
                             cudaFuncAttributeMaxDynamicSharedMemorySize,
                             SMEM_BYTES);
        attr_set = true;
    }

    rvnn_single<<<1, 1024, SMEM_BYTES>>>(h, W_emb, W_fc, b_fc, y);
}

// round 9
// speedup vs baseline: 1.5556x; 1.5556x over previous
#include <cuda_runtime.h>
#include <cooperative_groups.h>

namespace cg = cooperative_groups;

// y[b,c] = b_fc[c] + sum_f h[b,0,f] * V[c,f],  V = W_fc @ W_emb  ([2,768])
// (TreeLSTM scan in the reference is dead code; adj and recurrent weights unused.)
// B=32, N=128, FI=768, FO=128.
//
// ONE node: an 8-CTA cluster. CTA r owns f-slice [96r, 96r+96):
//   - V[c, slice]    : o-sum is CTA-local (f-partition => no cross-CTA reduce for V)
//   - y partial      : CTA-local over its 96 f's
//   - final 64-float : rank 0 gathers peers' partials via DSMEM after cluster.sync
// Spreads the 480 KB stream over 8 SMs (one SM's L1 path caps at ~54 GB/s, R8).

#define B_   32
#define N_   128
#define FI_  768
#define FO_  128
#define CSZ  8          // cluster size
#define FS   (FI_/CSZ)  // 96 f per CTA
#define FQ   (FS/4)     // 24 quads per CTA
#define NT   384        // 16 o-groups x 24 quads

__global__ __launch_bounds__(NT, 1) __cluster_dims__(CSZ, 1, 1)
void rvnn_cluster(const float* __restrict__ h,      // [B,N,FI]
                  const float* __restrict__ W_emb,  // [FO,FI]
                  const float* __restrict__ W_fc,   // [2,FO]
                  const float* __restrict__ b_fc,   // [2]
                  float* __restrict__ y)            // [B,2]
{
    __shared__ float4 s_part[16][2][FQ];   // per-o-group V partials
    __shared__ float4 s_V[2][FQ];
    __shared__ float4 s_h[B_][FQ + 1];     // +1 quad pad: rotate banks across b
    __shared__ float  s_y[64];             // this CTA's y partials [b*2+c]

    cg::cluster_group cluster = cg::this_cluster();
    const unsigned rank = cluster.block_rank();
    const int t  = threadIdx.x;
    const int g  = t / FQ;                 // o-group 0..15 (8 o's each)
    const int fq = t % FQ;                 // f-quad within slice 0..23

    const float4* wemb4 = reinterpret_cast<const float4*>(W_emb);

    // ---- Phase 1a: V partials over this thread's 8 o's at quad fq ----
    float4 a0 = make_float4(0.f, 0.f, 0.f, 0.f);
    float4 a1 = make_float4(0.f, 0.f, 0.f, 0.f);
    #pragma unroll
    for (int j = 0; j < 8; ++j) {
        const int o = g * 8 + j;
        const float f0 = __ldg(&W_fc[o]);          // broadcast
        const float f1 = __ldg(&W_fc[FO_ + o]);
        float4 w = __ldg(&wemb4[(size_t)o * (FI_/4) + rank * FQ + fq]);
        a0.x = fmaf(f0, w.x, a0.x); a0.y = fmaf(f0, w.y, a0.y);
        a0.z = fmaf(f0, w.z, a0.z); a0.w = fmaf(f0, w.w, a0.w);
        a1.x = fmaf(f1, w.x, a1.x); a1.y = fmaf(f1, w.y, a1.y);
        a1.z = fmaf(f1, w.z, a1.z); a1.w = fmaf(f1, w.w, a1.w);
    }
    s_part[g][0][fq] = a0;
    s_part[g][1][fq] = a1;

    // ---- Phase 1b: stage h[:, 0, f-slice] (2 quads per thread) ----
    #pragma unroll
    for (int r2 = 0; r2 < 2; ++r2) {
        const int idx = r2 * NT + t;               // 0..767 = b*24 + q
        const int b = idx / FQ, q = idx % FQ;
        s_h[b][q] = __ldg(reinterpret_cast<const float4*>(
                        h + (size_t)b * N_ * FI_ + rank * FS) + q);
    }
    __syncthreads();

    // ---- Fold 16 o-group partials into V slice ----
    if (t < 2 * FQ) {
        const int c = t / FQ, q = t % FQ;
        float4 s = make_float4(0.f, 0.f, 0.f, 0.f);
        #pragma unroll
        for (int k = 0; k < 16; ++k) {
            float4 p = s_part[k][c][q];
            s.x += p.x; s.y += p.y; s.z += p.z; s.w += p.w;
        }
        s_V[c][q] = s;
    }
    __syncthreads();

    // ---- Phase 2: partial y[b,c] over this CTA's 24 quads ----
    if (t < 64) {
        const int b = t >> 1, c = t & 1;
        float acc = 0.f;
        #pragma unroll
        for (int q = 0; q < FQ; ++q) {
            float4 hv = s_h[b][q];
            float4 vv = s_V[c][q];
            acc = fmaf(hv.x, vv.x, fmaf(hv.y, vv.y,
                  fmaf(hv.z, vv.z, fmaf(hv.w, vv.w, acc))));
        }
        s_y[t] = acc;
    }

    // ---- Cross-CTA reduce via DSMEM ----
    cluster.sync();                                // all partials visible

    if (rank == 0 && t < 64) {
        float total = 0.f;
        #pragma unroll
        for (int r = 0; r < CSZ; ++r) {
            const float* peer = cluster.map_shared_rank(s_y, r);
            total += peer[t];                      // 8 independent DSMEM loads
        }
        y[t] = total + __ldg(&b_fc[t & 1]);
    }

    cluster.sync();                                // keep peers resident for reads
}

extern "C" void kernel_launch(void* const* d_in, const int* in_sizes, int n_in,
                              void* d_out, int out_size)
{
    // metadata order: h, adj, W_emb, W_ioux, b_ioux, W_iouh, b_iouh,
    //                 W_coux, b_coux, W_couh, b_couh, W_fc, b_fc
    const float* h     = (const float*)d_in[0];
    const float* W_emb = (const float*)d_in[2];
    const float* W_fc  = (const float*)d_in[11];
    const float* b_fc  = (const float*)d_in[12];
    float* y = (float*)d_out;

    rvnn_cluster<<<CSZ, NT>>>(h, W_emb, W_fc, b_fc, y);
}

// round 10
// speedup vs baseline: 1.5628x; 1.0047x over previous
#include <cuda_runtime.h>
#include <cooperative_groups.h>

namespace cg = cooperative_groups;

// y[b,c] = b_fc[c] + sum_f h[b,0,f] * V[c,f],  V = W_fc @ W_emb  ([2,768])
// (TreeLSTM scan in the reference is dead code; adj and recurrent weights unused.)
// B=32, N=128, FI=768, FO=128.
//
// ONE node, 8-CTA cluster, f-partitioned. PUSH-model reduction:
// every CTA stores its 64 partial y's into rank 0's smem (DSMEM ST, latency
// not exposed), then ONE cluster.sync (arrive.release orders the stores),
// then rank 0 sums from its OWN smem and writes y. Peers exit immediately.

#define B_   32
#define N_   128
#define FI_  768
#define FO_  128
#define CSZ  8          // cluster size
#define FS   (FI_/CSZ)  // 96 f per CTA
#define FQ   (FS/4)     // 24 quads per CTA
#define NT   384        // 16 o-groups x 24 quads

__global__ __launch_bounds__(NT, 1) __cluster_dims__(CSZ, 1, 1)
void rvnn_cluster2(const float* __restrict__ h,      // [B,N,FI]
                   const float* __restrict__ W_emb,  // [FO,FI]
                   const float* __restrict__ W_fc,   // [2,FO]
                   const float* __restrict__ b_fc,   // [2]
                   float* __restrict__ y)            // [B,2]
{
    __shared__ float4 s_part[16][2][FQ];   // per-o-group V partials
    __shared__ float4 s_V[2][FQ];
    __shared__ float4 s_h[B_][FQ + 1];     // pad: rotate banks across b
    __shared__ float  s_red[CSZ][64];      // rank 0 receives all partials here

    cg::cluster_group cluster = cg::this_cluster();
    const unsigned rank = cluster.block_rank();
    const int t  = threadIdx.x;
    const int g  = t / FQ;                 // o-group 0..15 (8 o's each)
    const int fq = t % FQ;                 // f-quad within slice 0..23

    const float4* wemb4 = reinterpret_cast<const float4*>(W_emb);

    // ---- Front-batch every global access into one latency round ----
    const float bf = __ldg(&b_fc[t & 1]);  // bias (used by rank 0, t<64)

    float4 hv0, hv1;                       // h staging payload (2 quads/thread)
    {
        const int i0 = t, i1 = NT + t;     // idx = b*FQ + q
        hv0 = __ldg(reinterpret_cast<const float4*>(
                  h + (size_t)(i0 / FQ) * N_ * FI_ + rank * FS) + (i0 % FQ));
        hv1 = __ldg(reinterpret_cast<const float4*>(
                  h + (size_t)(i1 / FQ) * N_ * FI_ + rank * FS) + (i1 % FQ));
    }

    float4 w[8];                           // this thread's 8 W_emb quads
    float  f0[8], f1[8];
    #pragma unroll
    for (int j = 0; j < 8; ++j) {
        const int o = g * 8 + j;
        w[j]  = __ldg(&wemb4[(size_t)o * (FI_/4) + rank * FQ + fq]);
        f0[j] = __ldg(&W_fc[o]);
        f1[j] = __ldg(&W_fc[FO_ + o]);
    }

    // ---- Phase 1: V partials (pure FMA on registers) ----
    float4 a0 = make_float4(0.f, 0.f, 0.f, 0.f);
    float4 a1 = make_float4(0.f, 0.f, 0.f, 0.f);
    #pragma unroll
    for (int j = 0; j < 8; ++j) {
        a0.x = fmaf(f0[j], w[j].x, a0.x); a0.y = fmaf(f0[j], w[j].y, a0.y);
        a0.z = fmaf(f0[j], w[j].z, a0.z); a0.w = fmaf(f0[j], w[j].w, a0.w);
        a1.x = fmaf(f1[j], w[j].x, a1.x); a1.y = fmaf(f1[j], w[j].y, a1.y);
        a1.z = fmaf(f1[j], w[j].z, a1.z); a1.w = fmaf(f1[j], w[j].w, a1.w);
    }
    s_part[g][0][fq] = a0;
    s_part[g][1][fq] = a1;

    s_h[t / FQ][t % FQ]               = hv0;
    s_h[(NT + t) / FQ][(NT + t) % FQ] = hv1;
    __syncthreads();

    // ---- Fold 16 o-group partials into V slice ----
    if (t < 2 * FQ) {
        const int c = t / FQ, q = t % FQ;
        float4 s = make_float4(0.f, 0.f, 0.f, 0.f);
        #pragma unroll
        for (int k = 0; k < 16; ++k) {
            float4 p = s_part[k][c][q];
            s.x += p.x; s.y += p.y; s.z += p.z; s.w += p.w;
        }
        s_V[c][q] = s;
    }
    __syncthreads();

    // ---- Phase 2: partial y[b,c] over this CTA's 24 quads; PUSH to rank 0 ----
    if (t < 64) {
        const int b = t >> 1, c = t & 1;
        float acc = 0.f;
        #pragma unroll
        for (int q = 0; q < FQ; ++q) {
            float4 hq = s_h[b][q];
            float4 vv = s_V[c][q];
            acc = fmaf(hq.x, vv.x, fmaf(hq.y, vv.y,
                  fmaf(hq.z, vv.z, fmaf(hq.w, vv.w, acc))));
        }
        // Remote store into rank 0's s_red[rank][t] (local store if rank==0).
        float* dst = cluster.map_shared_rank(&s_red[rank][0], 0);
        dst[t] = acc;
    }

    // ---- ONE cluster barrier: arrive.release orders the DSMEM stores ----
    cluster.sync();

    // Rank 0 reduces from its OWN smem (no remote loads); peers just exit.
    if (rank == 0 && t < 64) {
        float total = 0.f;
        #pragma unroll
        for (int r = 0; r < CSZ; ++r)
            total += s_red[r][t];
        y[t] = total + bf;
    }
}

extern "C" void kernel_launch(void* const* d_in, const int* in_sizes, int n_in,
                              void* d_out, int out_size)
{
    // metadata order: h, adj, W_emb, W_ioux, b_ioux, W_iouh, b_iouh,
    //                 W_coux, b_coux, W_couh, b_couh, W_fc, b_fc
    const float* h     = (const float*)d_in[0];
    const float* W_emb = (const float*)d_in[2];
    const float* W_fc  = (const float*)d_in[11];
    const float* b_fc  = (const float*)d_in[12];
    float* y = (float*)d_out;

    rvnn_cluster2<<<CSZ, NT>>>(h, W_emb, W_fc, b_fc, y);
}